// round 2
// baseline (speedup 1.0000x reference)
#include <cuda_runtime.h>

// Problem constants
#define B_   256
#define T_   256
#define C_   384
#define NH_  8
#define HD_  48
#define M_   (B_ * T_)        // 65536 rows
#define N1_  (3 * C_)         // 1152 qkv outputs
#define QKV_STRIDE 25165824   // B*T*C elements per q/k/v region

// Scratch (allocation-guard-safe: static __device__ globals)
// g_qkv: [3][B][NH][T][HD]  (q, k, v regions)
// g_att: [B][T][C]          (attention output, heads recombined)
__device__ float g_qkv[3ull * QKV_STRIDE];
__device__ float g_att[(size_t)QKV_STRIDE];

// ---------------------------------------------------------------------------
// GEMM 1: qkv = x @ attn_w^T + attn_b, scattered into head-major Q/K/V.
// A [M,384] row-major (K contiguous), W [1152,384] row-major (K contiguous).
// 128x128 block tile, BK=16, 256 threads, 8x8 per thread.
// ---------------------------------------------------------------------------
__global__ __launch_bounds__(256) void gemm_qkv_kernel(
    const float* __restrict__ A,
    const float* __restrict__ W,
    const float* __restrict__ bias)
{
    constexpr int K  = 384;
    constexpr int BK = 16;
    __shared__ float As[BK][128];
    __shared__ float Bs[BK][128];

    const int tid   = threadIdx.x;
    const int mBase = blockIdx.y * 128;
    const int nBase = blockIdx.x * 128;

    const int lr  = tid >> 2;            // load row within 64-row half
    const int lc  = (tid & 3) * 4;       // k-chunk (float4) within BK
    const int ty4 = (tid >> 4) * 4;      // m micro-tile base
    const int tx4 = (tid & 15) * 4;      // n micro-tile base

    float acc[8][8];
#pragma unroll
    for (int i = 0; i < 8; ++i)
#pragma unroll
        for (int j = 0; j < 8; ++j) acc[i][j] = 0.f;

    const float* Ap0 = A + (size_t)(mBase + lr) * K + lc;
    const float* Ap1 = Ap0 + (size_t)64 * K;
    const float* Wp0 = W + (size_t)(nBase + lr) * K + lc;
    const float* Wp1 = Wp0 + (size_t)64 * K;

    for (int kt = 0; kt < K; kt += BK) {
        float4 a0 = *(const float4*)(Ap0 + kt);
        float4 a1 = *(const float4*)(Ap1 + kt);
        float4 b0 = *(const float4*)(Wp0 + kt);
        float4 b1 = *(const float4*)(Wp1 + kt);

        As[lc + 0][lr]      = a0.x; As[lc + 1][lr]      = a0.y;
        As[lc + 2][lr]      = a0.z; As[lc + 3][lr]      = a0.w;
        As[lc + 0][lr + 64] = a1.x; As[lc + 1][lr + 64] = a1.y;
        As[lc + 2][lr + 64] = a1.z; As[lc + 3][lr + 64] = a1.w;
        Bs[lc + 0][lr]      = b0.x; Bs[lc + 1][lr]      = b0.y;
        Bs[lc + 2][lr]      = b0.z; Bs[lc + 3][lr]      = b0.w;
        Bs[lc + 0][lr + 64] = b1.x; Bs[lc + 1][lr + 64] = b1.y;
        Bs[lc + 2][lr + 64] = b1.z; Bs[lc + 3][lr + 64] = b1.w;
        __syncthreads();

#pragma unroll
        for (int k = 0; k < BK; ++k) {
            float4 fa0 = *(const float4*)&As[k][ty4];
            float4 fa1 = *(const float4*)&As[k][ty4 + 64];
            float4 fb0 = *(const float4*)&Bs[k][tx4];
            float4 fb1 = *(const float4*)&Bs[k][tx4 + 64];
            float av[8] = {fa0.x, fa0.y, fa0.z, fa0.w, fa1.x, fa1.y, fa1.z, fa1.w};
            float bv[8] = {fb0.x, fb0.y, fb0.z, fb0.w, fb1.x, fb1.y, fb1.z, fb1.w};
#pragma unroll
            for (int i = 0; i < 8; ++i)
#pragma unroll
                for (int j = 0; j < 8; ++j)
                    acc[i][j] = fmaf(av[i], bv[j], acc[i][j]);
        }
        __syncthreads();
    }

    // Epilogue: add bias, scatter into head-major q/k/v scratch.
#pragma unroll
    for (int i = 0; i < 8; ++i) {
        const int m = mBase + ty4 + (i & 3) + ((i >> 2) << 6);
        const int b = m >> 8;        // / T_
        const int t = m & 255;       // % T_
#pragma unroll
        for (int j = 0; j < 8; ++j) {
            const int o = nBase + tx4 + (j & 3) + ((j >> 2) << 6);
            const float v = acc[i][j] + bias[o];
            const int which = o / C_;
            const int c = o - which * C_;
            const int h = c / HD_;
            const int d = c - h * HD_;
            const size_t dst = (size_t)which * QKV_STRIDE
                             + ((size_t)((b * NH_ + h) * T_ + t)) * HD_ + d;
            g_qkv[dst] = v;
        }
    }
}

// ---------------------------------------------------------------------------
// Attention: one CTA per (b, head); one thread per query row t.
// K/V tiled through static smem in two 128-row tiles (48 KB total).
// Online softmax in chunks of 8 keys.
// ---------------------------------------------------------------------------
__global__ __launch_bounds__(256) void attn_kernel()
{
    __shared__ float sK[128 * HD_];
    __shared__ float sV[128 * HD_];

    const int bh = blockIdx.x;                 // b*NH + h
    const size_t base = (size_t)bh * (T_ * HD_);
    const float* Qg = g_qkv + base;
    const float* Kg = g_qkv + (size_t)QKV_STRIDE + base;
    const float* Vg = g_qkv + 2ull * QKV_STRIDE + base;

    const int t = threadIdx.x;

    float q[HD_];
#pragma unroll
    for (int c = 0; c < 12; ++c) {
        float4 v = ((const float4*)(Qg + (size_t)t * HD_))[c];
        q[c * 4 + 0] = v.x; q[c * 4 + 1] = v.y;
        q[c * 4 + 2] = v.z; q[c * 4 + 3] = v.w;
    }

    const float scale   = 0.14433756729740645f;   // 1/sqrt(48)
    const float NEG_INF = __int_as_float(0xff800000);
    float mrow = NEG_INF;
    float l = 0.f;
    float acc[HD_];
#pragma unroll
    for (int d = 0; d < HD_; ++d) acc[d] = 0.f;

    for (int tile = 0; tile < 2; ++tile) {
        const int jbase = tile * 128;
        __syncthreads();   // all consumers of previous tile done
#pragma unroll
        for (int i = 0; i < 6; ++i) {
            const int idx = t + i * 256;   // float4 index, 1536 per array
            ((float4*)sK)[idx] = ((const float4*)(Kg + (size_t)jbase * HD_))[idx];
            ((float4*)sV)[idx] = ((const float4*)(Vg + (size_t)jbase * HD_))[idx];
        }
        __syncthreads();

        if (t < jbase) continue;           // both barriers already passed
        const int jmax = min(t - jbase, 127);

        for (int j0 = 0; j0 <= jmax; j0 += 8) {
            float s[8];
#pragma unroll
            for (int i = 0; i < 8; ++i) {
                const float4* kr = (const float4*)(sK + (j0 + i) * HD_);
                float d0 = 0.f, d1 = 0.f, d2 = 0.f, d3 = 0.f;
#pragma unroll
                for (int c = 0; c < 12; ++c) {
                    float4 kv = kr[c];
                    d0 = fmaf(q[c * 4 + 0], kv.x, d0);
                    d1 = fmaf(q[c * 4 + 1], kv.y, d1);
                    d2 = fmaf(q[c * 4 + 2], kv.z, d2);
                    d3 = fmaf(q[c * 4 + 3], kv.w, d3);
                }
                const float dsum = (d0 + d1) + (d2 + d3);
                s[i] = (j0 + i <= jmax) ? dsum * scale : NEG_INF;
            }
            float cm = s[0];
#pragma unroll
            for (int i = 1; i < 8; ++i) cm = fmaxf(cm, s[i]);
            const float mnew = fmaxf(mrow, cm);
            const float corr = __expf(mrow - mnew);   // exp(-inf)=0 on first chunk
            float p[8];
            float psum = 0.f;
#pragma unroll
            for (int i = 0; i < 8; ++i) { p[i] = __expf(s[i] - mnew); psum += p[i]; }
            l = l * corr + psum;
#pragma unroll
            for (int d = 0; d < HD_; ++d) acc[d] *= corr;
#pragma unroll
            for (int i = 0; i < 8; ++i) {
                const float4* vr = (const float4*)(sV + (j0 + i) * HD_);
#pragma unroll
                for (int c = 0; c < 12; ++c) {
                    float4 vv = vr[c];
                    acc[c * 4 + 0] = fmaf(p[i], vv.x, acc[c * 4 + 0]);
                    acc[c * 4 + 1] = fmaf(p[i], vv.y, acc[c * 4 + 1]);
                    acc[c * 4 + 2] = fmaf(p[i], vv.z, acc[c * 4 + 2]);
                    acc[c * 4 + 3] = fmaf(p[i], vv.w, acc[c * 4 + 3]);
                }
            }
            mrow = mnew;
        }
    }

    const float inv = 1.f / l;
    const int b = bh >> 3, h = bh & 7;
    float* dst = g_att + (size_t)(b * T_ + t) * C_ + h * HD_;
#pragma unroll
    for (int c = 0; c < 12; ++c) {
        float4 v;
        v.x = acc[c * 4 + 0] * inv; v.y = acc[c * 4 + 1] * inv;
        v.z = acc[c * 4 + 2] * inv; v.w = acc[c * 4 + 3] * inv;
        ((float4*)dst)[c] = v;
    }
}

// ---------------------------------------------------------------------------
// GEMM 2: out = att @ proj_w^T + proj_b.  Same tiling as GEMM 1.
// ---------------------------------------------------------------------------
__global__ __launch_bounds__(256) void gemm_proj_kernel(
    const float* __restrict__ W,     // proj_w [384,384]
    const float* __restrict__ bias,  // proj_b [384]
    float* __restrict__ out)         // [M, 384]
{
    constexpr int K  = 384;
    constexpr int BK = 16;
    __shared__ float As[BK][128];
    __shared__ float Bs[BK][128];

    const int tid   = threadIdx.x;
    const int mBase = blockIdx.y * 128;
    const int nBase = blockIdx.x * 128;

    const int lr  = tid >> 2;
    const int lc  = (tid & 3) * 4;
    const int ty4 = (tid >> 4) * 4;
    const int tx4 = (tid & 15) * 4;

    float acc[8][8];
#pragma unroll
    for (int i = 0; i < 8; ++i)
#pragma unroll
        for (int j = 0; j < 8; ++j) acc[i][j] = 0.f;

    const float* Ap0 = g_att + (size_t)(mBase + lr) * K + lc;
    const float* Ap1 = Ap0 + (size_t)64 * K;
    const float* Wp0 = W + (size_t)(nBase + lr) * K + lc;
    const float* Wp1 = Wp0 + (size_t)64 * K;

    for (int kt = 0; kt < K; kt += BK) {
        float4 a0 = *(const float4*)(Ap0 + kt);
        float4 a1 = *(const float4*)(Ap1 + kt);
        float4 b0 = *(const float4*)(Wp0 + kt);
        float4 b1 = *(const float4*)(Wp1 + kt);

        As[lc + 0][lr]      = a0.x; As[lc + 1][lr]      = a0.y;
        As[lc + 2][lr]      = a0.z; As[lc + 3][lr]      = a0.w;
        As[lc + 0][lr + 64] = a1.x; As[lc + 1][lr + 64] = a1.y;
        As[lc + 2][lr + 64] = a1.z; As[lc + 3][lr + 64] = a1.w;
        Bs[lc + 0][lr]      = b0.x; Bs[lc + 1][lr]      = b0.y;
        Bs[lc + 2][lr]      = b0.z; Bs[lc + 3][lr]      = b0.w;
        Bs[lc + 0][lr + 64] = b1.x; Bs[lc + 1][lr + 64] = b1.y;
        Bs[lc + 2][lr + 64] = b1.z; Bs[lc + 3][lr + 64] = b1.w;
        __syncthreads();

#pragma unroll
        for (int k = 0; k < BK; ++k) {
            float4 fa0 = *(const float4*)&As[k][ty4];
            float4 fa1 = *(const float4*)&As[k][ty4 + 64];
            float4 fb0 = *(const float4*)&Bs[k][tx4];
            float4 fb1 = *(const float4*)&Bs[k][tx4 + 64];
            float av[8] = {fa0.x, fa0.y, fa0.z, fa0.w, fa1.x, fa1.y, fa1.z, fa1.w};
            float bv[8] = {fb0.x, fb0.y, fb0.z, fb0.w, fb1.x, fb1.y, fb1.z, fb1.w};
#pragma unroll
            for (int i = 0; i < 8; ++i)
#pragma unroll
                for (int j = 0; j < 8; ++j)
                    acc[i][j] = fmaf(av[i], bv[j], acc[i][j]);
        }
        __syncthreads();
    }

    const float4 bia0 = *(const float4*)(bias + nBase + tx4);
    const float4 bia1 = *(const float4*)(bias + nBase + tx4 + 64);
#pragma unroll
    for (int i = 0; i < 8; ++i) {
        const int m = mBase + ty4 + (i & 3) + ((i >> 2) << 6);
        float* orow = out + (size_t)m * K;
        float4 v0, v1;
        v0.x = acc[i][0] + bia0.x; v0.y = acc[i][1] + bia0.y;
        v0.z = acc[i][2] + bia0.z; v0.w = acc[i][3] + bia0.w;
        v1.x = acc[i][4] + bia1.x; v1.y = acc[i][5] + bia1.y;
        v1.z = acc[i][6] + bia1.z; v1.w = acc[i][7] + bia1.w;
        *(float4*)(orow + nBase + tx4)      = v0;
        *(float4*)(orow + nBase + tx4 + 64) = v1;
    }
}

// ---------------------------------------------------------------------------
extern "C" void kernel_launch(void* const* d_in, const int* in_sizes, int n_in,
                              void* d_out, int out_size)
{
    const float* x      = (const float*)d_in[0];
    const float* attn_w = (const float*)d_in[1];
    const float* attn_b = (const float*)d_in[2];
    const float* proj_w = (const float*)d_in[3];
    const float* proj_b = (const float*)d_in[4];
    float* out = (float*)d_out;

    // qkv = x @ attn_w^T + attn_b  (scatter into head-major scratch)
    gemm_qkv_kernel<<<dim3(N1_ / 128, M_ / 128), 256>>>(x, attn_w, attn_b);

    // causal flash attention per (b, head)
    attn_kernel<<<B_ * NH_, 256>>>();

    // out = att @ proj_w^T + proj_b
    gemm_proj_kernel<<<dim3(C_ / 128, M_ / 128), 256>>>(proj_w, proj_b, out);
}

// round 3
// speedup vs baseline: 1.8155x; 1.8155x over previous
#include <cuda_runtime.h>
#include <stdint.h>

// Problem constants
#define B_   256
#define T_   256
#define C_   384
#define NH_  8
#define HD_  48
#define M_   (B_ * T_)        // 65536 rows
#define N1_  (3 * C_)         // 1152 qkv outputs
#define QKV_STRIDE 25165824   // B*T*C elements per q/k/v region

// Scratch (allocation-guard-safe: static __device__ globals)
__device__ float g_qkv[3ull * QKV_STRIDE];   // [3][B][NH][T][HD]
__device__ float g_att[(size_t)QKV_STRIDE];  // [B][T][C]

// ---------------------------------------------------------------------------
// tf32 helpers
// ---------------------------------------------------------------------------
__device__ __forceinline__ uint32_t f2tf(float f) {
    uint32_t u;
    asm("cvt.rna.tf32.f32 %0, %1;" : "=r"(u) : "f"(f));
    return u;
}

__device__ __forceinline__ void mma_tf32(
    float& c0, float& c1, float& c2, float& c3,
    uint32_t a0, uint32_t a1, uint32_t a2, uint32_t a3,
    uint32_t b0, uint32_t b1)
{
    asm volatile(
        "mma.sync.aligned.m16n8k8.row.col.f32.tf32.tf32.f32 "
        "{%0,%1,%2,%3}, {%4,%5,%6,%7}, {%8,%9}, {%0,%1,%2,%3};"
        : "+f"(c0), "+f"(c1), "+f"(c2), "+f"(c3)
        : "r"(a0), "r"(a1), "r"(a2), "r"(a3), "r"(b0), "r"(b1));
}

// ---------------------------------------------------------------------------
// tf32 tensor-core GEMM core: 128x128 tile, BK=32, 256 thr = 8 warps (2m x 4n),
// warp tile 64x32 = 4x4 m16n8k8 atoms.  A [M,K] row-major, W [N,K] row-major
// (= col-major B for row.col mma).  K = 384.
// Shared smem layout: [32][SSTR] k-major, stride 133 for bank spread.
// ---------------------------------------------------------------------------
#define SSTR 133

struct GemmFrag {
    float acc[4][4][4];   // [m-atom][n-atom][reg]
    int gid, ctg, wmB, wnB;
};

// Runs the full K-loop; acc left in f.acc.  Both A and W assumed 128-row
// aligned at (mBase,*) and (nBase,*); K=384 exactly.
__device__ __forceinline__ void gemm_core(
    const float* __restrict__ A, const float* __restrict__ W,
    int mBase, int nBase, uint32_t (*As)[SSTR], uint32_t (*Bs)[SSTR],
    GemmFrag& f)
{
    const int tid  = threadIdx.x;
    const int lane = tid & 31;
    const int warp = tid >> 5;
    f.gid = lane >> 2;
    f.ctg = lane & 3;
    f.wmB = (warp >> 2) * 64;   // warp m base within tile (0 or 64)
    f.wnB = (warp & 3) * 32;    // warp n base within tile (0,32,64,96)

#pragma unroll
    for (int i = 0; i < 4; ++i)
#pragma unroll
        for (int j = 0; j < 4; ++j)
#pragma unroll
            for (int r = 0; r < 4; ++r) f.acc[i][j][r] = 0.f;

    const int lrow = tid >> 3;         // 0..31
    const int lcol = (tid & 7) * 4;    // 0..28

    for (int kt = 0; kt < 384; kt += 32) {
        // global loads first (overlap with previous tile's compute)
        float4 av[4], wv[4];
#pragma unroll
        for (int i = 0; i < 4; ++i) {
            av[i] = *(const float4*)(A + (size_t)(mBase + lrow + 32 * i) * 384 + kt + lcol);
            wv[i] = *(const float4*)(W + (size_t)(nBase + lrow + 32 * i) * 384 + kt + lcol);
        }
        __syncthreads();
#pragma unroll
        for (int i = 0; i < 4; ++i) {
            const int r = lrow + 32 * i;
            As[lcol + 0][r] = f2tf(av[i].x);
            As[lcol + 1][r] = f2tf(av[i].y);
            As[lcol + 2][r] = f2tf(av[i].z);
            As[lcol + 3][r] = f2tf(av[i].w);
            Bs[lcol + 0][r] = f2tf(wv[i].x);
            Bs[lcol + 1][r] = f2tf(wv[i].y);
            Bs[lcol + 2][r] = f2tf(wv[i].z);
            Bs[lcol + 3][r] = f2tf(wv[i].w);
        }
        __syncthreads();

#pragma unroll
        for (int kk = 0; kk < 32; kk += 8) {
            uint32_t a[4][4], b[4][2];
#pragma unroll
            for (int im = 0; im < 4; ++im) {
                const int m0 = f.wmB + im * 16 + f.gid;
                a[im][0] = As[kk + f.ctg][m0];
                a[im][1] = As[kk + f.ctg][m0 + 8];
                a[im][2] = As[kk + f.ctg + 4][m0];
                a[im][3] = As[kk + f.ctg + 4][m0 + 8];
            }
#pragma unroll
            for (int jn = 0; jn < 4; ++jn) {
                const int n0 = f.wnB + jn * 8 + f.gid;
                b[jn][0] = Bs[kk + f.ctg][n0];
                b[jn][1] = Bs[kk + f.ctg + 4][n0];
            }
#pragma unroll
            for (int im = 0; im < 4; ++im)
#pragma unroll
                for (int jn = 0; jn < 4; ++jn)
                    mma_tf32(f.acc[im][jn][0], f.acc[im][jn][1],
                             f.acc[im][jn][2], f.acc[im][jn][3],
                             a[im][0], a[im][1], a[im][2], a[im][3],
                             b[jn][0], b[jn][1]);
        }
    }
}

// ---------------------------------------------------------------------------
// GEMM 1: qkv = x @ attn_w^T + attn_b, scattered head-major into g_qkv.
// ---------------------------------------------------------------------------
__global__ __launch_bounds__(256) void gemm_qkv_kernel(
    const float* __restrict__ A,
    const float* __restrict__ W,
    const float* __restrict__ bias)
{
    __shared__ uint32_t As[32][SSTR];
    __shared__ uint32_t Bs[32][SSTR];
    const int mBase = blockIdx.y * 128;
    const int nBase = blockIdx.x * 128;

    GemmFrag f;
    gemm_core(A, W, mBase, nBase, As, Bs, f);

    // Epilogue: C fragment (im,jn): rows mBase+wmB+im*16+gid (+8 for regs 2,3),
    // cols nBase+wnB+jn*8+2*ctg (+1).  Pairs (c0,c1)/(c2,c3) are contiguous cols.
#pragma unroll
    for (int im = 0; im < 4; ++im) {
#pragma unroll
        for (int jn = 0; jn < 4; ++jn) {
            const int col = nBase + f.wnB + jn * 8 + 2 * f.ctg;
            const float2 bi = *(const float2*)(bias + col);
            const int which = col / C_;
            const int c = col - which * C_;
            const int h = c / HD_;
            const int d = c - h * HD_;   // even; pair never straddles a head
#pragma unroll
            for (int half = 0; half < 2; ++half) {
                const int row = mBase + f.wmB + im * 16 + f.gid + half * 8;
                const int b = row >> 8;
                const int t = row & 255;
                float2 v;
                v.x = f.acc[im][jn][half * 2 + 0] + bi.x;
                v.y = f.acc[im][jn][half * 2 + 1] + bi.y;
                const size_t dst = (size_t)which * QKV_STRIDE
                                 + ((size_t)((b * NH_ + h) * T_ + t)) * HD_ + d;
                *(float2*)(g_qkv + dst) = v;
            }
        }
    }
}

// ---------------------------------------------------------------------------
// GEMM 2: out = g_att @ proj_w^T + proj_b.
// ---------------------------------------------------------------------------
__global__ __launch_bounds__(256) void gemm_proj_kernel(
    const float* __restrict__ W,
    const float* __restrict__ bias,
    float* __restrict__ out)
{
    __shared__ uint32_t As[32][SSTR];
    __shared__ uint32_t Bs[32][SSTR];
    const int mBase = blockIdx.y * 128;
    const int nBase = blockIdx.x * 128;

    GemmFrag f;
    gemm_core(g_att, W, mBase, nBase, As, Bs, f);

#pragma unroll
    for (int im = 0; im < 4; ++im) {
#pragma unroll
        for (int jn = 0; jn < 4; ++jn) {
            const int col = nBase + f.wnB + jn * 8 + 2 * f.ctg;
            const float2 bi = *(const float2*)(bias + col);
#pragma unroll
            for (int half = 0; half < 2; ++half) {
                const int row = mBase + f.wmB + im * 16 + f.gid + half * 8;
                float2 v;
                v.x = f.acc[im][jn][half * 2 + 0] + bi.x;
                v.y = f.acc[im][jn][half * 2 + 1] + bi.y;
                *(float2*)(out + (size_t)row * C_ + col) = v;
            }
        }
    }
}

// ---------------------------------------------------------------------------
// Attention: unchanged exact-fp32 flash attention, one CTA per (b, head).
// ---------------------------------------------------------------------------
__global__ __launch_bounds__(256) void attn_kernel()
{
    __shared__ float sK[128 * HD_];
    __shared__ float sV[128 * HD_];

    const int bh = blockIdx.x;
    const size_t base = (size_t)bh * (T_ * HD_);
    const float* Qg = g_qkv + base;
    const float* Kg = g_qkv + (size_t)QKV_STRIDE + base;
    const float* Vg = g_qkv + 2ull * QKV_STRIDE + base;

    const int t = threadIdx.x;

    float q[HD_];
#pragma unroll
    for (int c = 0; c < 12; ++c) {
        float4 v = ((const float4*)(Qg + (size_t)t * HD_))[c];
        q[c * 4 + 0] = v.x; q[c * 4 + 1] = v.y;
        q[c * 4 + 2] = v.z; q[c * 4 + 3] = v.w;
    }

    const float scale   = 0.14433756729740645f;   // 1/sqrt(48)
    const float NEG_INF = __int_as_float(0xff800000);
    float mrow = NEG_INF;
    float l = 0.f;
    float acc[HD_];
#pragma unroll
    for (int d = 0; d < HD_; ++d) acc[d] = 0.f;

    for (int tile = 0; tile < 2; ++tile) {
        const int jbase = tile * 128;
        __syncthreads();
#pragma unroll
        for (int i = 0; i < 6; ++i) {
            const int idx = t + i * 256;
            ((float4*)sK)[idx] = ((const float4*)(Kg + (size_t)jbase * HD_))[idx];
            ((float4*)sV)[idx] = ((const float4*)(Vg + (size_t)jbase * HD_))[idx];
        }
        __syncthreads();

        if (t < jbase) continue;
        const int jmax = min(t - jbase, 127);

        for (int j0 = 0; j0 <= jmax; j0 += 8) {
            float s[8];
#pragma unroll
            for (int i = 0; i < 8; ++i) {
                const float4* kr = (const float4*)(sK + (j0 + i) * HD_);
                float d0 = 0.f, d1 = 0.f, d2 = 0.f, d3 = 0.f;
#pragma unroll
                for (int c = 0; c < 12; ++c) {
                    float4 kv = kr[c];
                    d0 = fmaf(q[c * 4 + 0], kv.x, d0);
                    d1 = fmaf(q[c * 4 + 1], kv.y, d1);
                    d2 = fmaf(q[c * 4 + 2], kv.z, d2);
                    d3 = fmaf(q[c * 4 + 3], kv.w, d3);
                }
                const float dsum = (d0 + d1) + (d2 + d3);
                s[i] = (j0 + i <= jmax) ? dsum * scale : NEG_INF;
            }
            float cm = s[0];
#pragma unroll
            for (int i = 1; i < 8; ++i) cm = fmaxf(cm, s[i]);
            const float mnew = fmaxf(mrow, cm);
            const float corr = __expf(mrow - mnew);
            float p[8];
            float psum = 0.f;
#pragma unroll
            for (int i = 0; i < 8; ++i) { p[i] = __expf(s[i] - mnew); psum += p[i]; }
            l = l * corr + psum;
#pragma unroll
            for (int d = 0; d < HD_; ++d) acc[d] *= corr;
#pragma unroll
            for (int i = 0; i < 8; ++i) {
                const float4* vr = (const float4*)(sV + (j0 + i) * HD_);
#pragma unroll
                for (int c = 0; c < 12; ++c) {
                    float4 vv = vr[c];
                    acc[c * 4 + 0] = fmaf(p[i], vv.x, acc[c * 4 + 0]);
                    acc[c * 4 + 1] = fmaf(p[i], vv.y, acc[c * 4 + 1]);
                    acc[c * 4 + 2] = fmaf(p[i], vv.z, acc[c * 4 + 2]);
                    acc[c * 4 + 3] = fmaf(p[i], vv.w, acc[c * 4 + 3]);
                }
            }
            mrow = mnew;
        }
    }

    const float inv = 1.f / l;
    const int b = bh >> 3, h = bh & 7;
    float* dst = g_att + (size_t)(b * T_ + t) * C_ + h * HD_;
#pragma unroll
    for (int c = 0; c < 12; ++c) {
        float4 v;
        v.x = acc[c * 4 + 0] * inv; v.y = acc[c * 4 + 1] * inv;
        v.z = acc[c * 4 + 2] * inv; v.w = acc[c * 4 + 3] * inv;
        ((float4*)dst)[c] = v;
    }
}

// ---------------------------------------------------------------------------
extern "C" void kernel_launch(void* const* d_in, const int* in_sizes, int n_in,
                              void* d_out, int out_size)
{
    const float* x      = (const float*)d_in[0];
    const float* attn_w = (const float*)d_in[1];
    const float* attn_b = (const float*)d_in[2];
    const float* proj_w = (const float*)d_in[3];
    const float* proj_b = (const float*)d_in[4];
    float* out = (float*)d_out;

    gemm_qkv_kernel<<<dim3(N1_ / 128, M_ / 128), 256>>>(x, attn_w, attn_b);
    attn_kernel<<<B_ * NH_, 256>>>();
    gemm_proj_kernel<<<dim3(C_ / 128, M_ / 128), 256>>>(proj_w, proj_b, out);
}

// round 4
// speedup vs baseline: 2.2772x; 1.2543x over previous
#include <cuda_runtime.h>
#include <stdint.h>

// Problem constants
#define B_   256
#define T_   256
#define C_   384
#define NH_  8
#define HD_  48
#define M_   (B_ * T_)        // 65536 rows
#define N1_  (3 * C_)         // 1152 qkv outputs
#define QKV_STRIDE 25165824   // B*T*C elements per q/k/v region

// Scratch (allocation-guard-safe: static __device__ globals)
__device__ float g_qkv[3ull * QKV_STRIDE];   // [3][B][NH][T][HD]
__device__ float g_att[(size_t)QKV_STRIDE];  // [B][T][C]

// ---------------------------------------------------------------------------
// tf32 / packed-f32x2 helpers
// ---------------------------------------------------------------------------
__device__ __forceinline__ uint32_t f2tf(float f) {
    uint32_t u;
    asm("cvt.rna.tf32.f32 %0, %1;" : "=r"(u) : "f"(f));
    return u;
}

__device__ __forceinline__ void mma_tf32(
    float& c0, float& c1, float& c2, float& c3,
    uint32_t a0, uint32_t a1, uint32_t a2, uint32_t a3,
    uint32_t b0, uint32_t b1)
{
    asm volatile(
        "mma.sync.aligned.m16n8k8.row.col.f32.tf32.tf32.f32 "
        "{%0,%1,%2,%3}, {%4,%5,%6,%7}, {%8,%9}, {%0,%1,%2,%3};"
        : "+f"(c0), "+f"(c1), "+f"(c2), "+f"(c3)
        : "r"(a0), "r"(a1), "r"(a2), "r"(a3), "r"(b0), "r"(b1));
}

typedef unsigned long long u64;

__device__ __forceinline__ u64 fma2(u64 a, u64 b, u64 c) {
    u64 d;
    asm("fma.rn.f32x2 %0, %1, %2, %3;" : "=l"(d) : "l"(a), "l"(b), "l"(c));
    return d;
}
__device__ __forceinline__ u64 mul2(u64 a, u64 b) {
    u64 d;
    asm("mul.rn.f32x2 %0, %1, %2;" : "=l"(d) : "l"(a), "l"(b));
    return d;
}
__device__ __forceinline__ u64 add2(u64 a, u64 b) {
    u64 d;
    asm("add.rn.f32x2 %0, %1, %2;" : "=l"(d) : "l"(a), "l"(b));
    return d;
}
__device__ __forceinline__ u64 pack2(float x, float y) {
    u64 d;
    asm("mov.b64 %0, {%1, %2};" : "=l"(d) : "f"(x), "f"(y));
    return d;
}
__device__ __forceinline__ float2 unpack2(u64 v) {
    float2 r;
    asm("mov.b64 {%0, %1}, %2;" : "=f"(r.x), "=f"(r.y) : "l"(v));
    return r;
}

// ---------------------------------------------------------------------------
// tf32 tensor-core GEMM core: 128x128 tile, BK=32, 256 thr = 8 warps (2m x 4n),
// warp tile 64x32 = 4x4 m16n8k8 atoms.  A [M,K] row-major, W [N,K] row-major.
//
// Smem in FRAGMENT ORDER:
//  A chunk (kb, am): 128 floats; element (m,k): am=m>>4, gid=m&7, r8=(m>>3)&1,
//    kb=k>>3, ctg=k&3, khalf=(k>>2)&1 -> addr = (kb*8+am)*128
//    + ((gid*4+ctg+kb)&31)*4 + (r8+2*khalf).    Reader: one LDS.128 per atom.
//  B chunk (kb, an): 64 floats; addr = (kb*16+an)*64 + ((gid*4+ctg+kb)&31)*2
//    + khalf.                                    Reader: one LDS.64 per atom.
// ---------------------------------------------------------------------------
struct GemmFrag {
    float acc[4][4][4];   // [m-atom][n-atom][reg]
    int gid, ctg, wmB, wnB, lane;
};

__device__ __forceinline__ void gemm_core(
    const float* __restrict__ A, const float* __restrict__ W,
    int mBase, int nBase, uint32_t* As, uint32_t* Bs, GemmFrag& f)
{
    const int tid  = threadIdx.x;
    f.lane = tid & 31;
    const int warp = tid >> 5;
    f.gid = f.lane >> 2;
    f.ctg = f.lane & 3;
    f.wmB = (warp >> 2) * 64;
    f.wnB = (warp & 3) * 32;

#pragma unroll
    for (int i = 0; i < 4; ++i)
#pragma unroll
        for (int j = 0; j < 4; ++j)
#pragma unroll
            for (int r = 0; r < 4; ++r) f.acc[i][j][r] = 0.f;

    const int lrow    = tid >> 3;        // 0..31
    const int lcol    = (tid & 7) * 4;   // 0..28
    const int kb_w    = lcol >> 3;       // 0..3
    const int khalf_w = (lcol >> 2) & 1;

    for (int kt = 0; kt < 384; kt += 32) {
        float4 av[4], wv[4];
#pragma unroll
        for (int i = 0; i < 4; ++i) {
            av[i] = *(const float4*)(A + (size_t)(mBase + lrow + 32 * i) * 384 + kt + lcol);
            wv[i] = *(const float4*)(W + (size_t)(nBase + lrow + 32 * i) * 384 + kt + lcol);
        }
        __syncthreads();
#pragma unroll
        for (int i = 0; i < 4; ++i) {
            const int m   = lrow + 32 * i;
            const int am  = m >> 4;
            const int an  = m >> 3;
            const int gw4 = (m & 7) * 4;
            const int r8  = (m >> 3) & 1;
            const int aBase = (kb_w * 8 + am) * 128 + r8 + 2 * khalf_w;
            const int bBase = (kb_w * 16 + an) * 64 + khalf_w;
            const float va[4] = {av[i].x, av[i].y, av[i].z, av[i].w};
            const float vb[4] = {wv[i].x, wv[i].y, wv[i].z, wv[i].w};
#pragma unroll
            for (int c = 0; c < 4; ++c) {
                const int ls = (gw4 + c + kb_w) & 31;
                As[aBase + ls * 4] = f2tf(va[c]);
                Bs[bBase + ls * 2] = f2tf(vb[c]);
            }
        }
        __syncthreads();

#pragma unroll
        for (int kb = 0; kb < 4; ++kb) {
            const int lsw = (f.lane + kb) & 31;
            uint32_t a[4][4], b[4][2];
#pragma unroll
            for (int im = 0; im < 4; ++im) {
                const int am = (f.wmB >> 4) + im;
                const uint4 t4 = *(const uint4*)&As[(kb * 8 + am) * 128 + lsw * 4];
                a[im][0] = t4.x; a[im][1] = t4.y; a[im][2] = t4.z; a[im][3] = t4.w;
            }
#pragma unroll
            for (int jn = 0; jn < 4; ++jn) {
                const int an = (f.wnB >> 3) + jn;
                const uint2 t2 = *(const uint2*)&Bs[(kb * 16 + an) * 64 + lsw * 2];
                b[jn][0] = t2.x; b[jn][1] = t2.y;
            }
#pragma unroll
            for (int im = 0; im < 4; ++im)
#pragma unroll
                for (int jn = 0; jn < 4; ++jn)
                    mma_tf32(f.acc[im][jn][0], f.acc[im][jn][1],
                             f.acc[im][jn][2], f.acc[im][jn][3],
                             a[im][0], a[im][1], a[im][2], a[im][3],
                             b[jn][0], b[jn][1]);
        }
    }
}

// ---------------------------------------------------------------------------
// GEMM 1: qkv = x @ attn_w^T + attn_b, scattered head-major into g_qkv.
// ---------------------------------------------------------------------------
__global__ __launch_bounds__(256) void gemm_qkv_kernel(
    const float* __restrict__ A,
    const float* __restrict__ W,
    const float* __restrict__ bias)
{
    __shared__ uint32_t As[4096];
    __shared__ uint32_t Bs[4096];
    const int mBase = blockIdx.y * 128;
    const int nBase = blockIdx.x * 128;

    GemmFrag f;
    gemm_core(A, W, mBase, nBase, As, Bs, f);

#pragma unroll
    for (int im = 0; im < 4; ++im) {
#pragma unroll
        for (int jn = 0; jn < 4; ++jn) {
            const int col = nBase + f.wnB + jn * 8 + 2 * f.ctg;
            const float2 bi = *(const float2*)(bias + col);
            const int which = col / C_;
            const int c = col - which * C_;
            const int h = c / HD_;
            const int d = c - h * HD_;   // even; pair never straddles a head
#pragma unroll
            for (int half = 0; half < 2; ++half) {
                const int row = mBase + f.wmB + im * 16 + f.gid + half * 8;
                const int b = row >> 8;
                const int t = row & 255;
                float2 v;
                v.x = f.acc[im][jn][half * 2 + 0] + bi.x;
                v.y = f.acc[im][jn][half * 2 + 1] + bi.y;
                const size_t dst = (size_t)which * QKV_STRIDE
                                 + ((size_t)((b * NH_ + h) * T_ + t)) * HD_ + d;
                *(float2*)(g_qkv + dst) = v;
            }
        }
    }
}

// ---------------------------------------------------------------------------
// GEMM 2: out = g_att @ proj_w^T + proj_b.
// ---------------------------------------------------------------------------
__global__ __launch_bounds__(256) void gemm_proj_kernel(
    const float* __restrict__ W,
    const float* __restrict__ bias,
    float* __restrict__ out)
{
    __shared__ uint32_t As[4096];
    __shared__ uint32_t Bs[4096];
    const int mBase = blockIdx.y * 128;
    const int nBase = blockIdx.x * 128;

    GemmFrag f;
    gemm_core(g_att, W, mBase, nBase, As, Bs, f);

#pragma unroll
    for (int im = 0; im < 4; ++im) {
#pragma unroll
        for (int jn = 0; jn < 4; ++jn) {
            const int col = nBase + f.wnB + jn * 8 + 2 * f.ctg;
            const float2 bi = *(const float2*)(bias + col);
#pragma unroll
            for (int half = 0; half < 2; ++half) {
                const int row = mBase + f.wmB + im * 16 + f.gid + half * 8;
                float2 v;
                v.x = f.acc[im][jn][half * 2 + 0] + bi.x;
                v.y = f.acc[im][jn][half * 2 + 1] + bi.y;
                *(float2*)(out + (size_t)row * C_ + col) = v;
            }
        }
    }
}

// ---------------------------------------------------------------------------
// Attention: exact-fp32 flash attention using packed fma.rn.f32x2.
// One CTA per (b, head), one thread per query row.
// ---------------------------------------------------------------------------
__global__ __launch_bounds__(256) void attn_kernel()
{
    __shared__ float sK[128 * HD_];
    __shared__ float sV[128 * HD_];

    const int bh = blockIdx.x;
    const size_t base = (size_t)bh * (T_ * HD_);
    const float* Qg = g_qkv + base;
    const float* Kg = g_qkv + (size_t)QKV_STRIDE + base;
    const float* Vg = g_qkv + 2ull * QKV_STRIDE + base;

    const int t = threadIdx.x;

    u64 q2[24];
    {
        const u64* qp = (const u64*)(Qg + (size_t)t * HD_);
#pragma unroll
        for (int i = 0; i < 24; ++i) q2[i] = qp[i];
    }

    const float scale   = 0.14433756729740645f;   // 1/sqrt(48)
    const float NEG_INF = __int_as_float(0xff800000);
    float mrow = NEG_INF;
    float l = 0.f;
    u64 acc2[24];
#pragma unroll
    for (int d = 0; d < 24; ++d) acc2[d] = 0ull;

    for (int tile = 0; tile < 2; ++tile) {
        const int jbase = tile * 128;
        __syncthreads();
#pragma unroll
        for (int i = 0; i < 6; ++i) {
            const int idx = t + i * 256;
            ((float4*)sK)[idx] = ((const float4*)(Kg + (size_t)jbase * HD_))[idx];
            ((float4*)sV)[idx] = ((const float4*)(Vg + (size_t)jbase * HD_))[idx];
        }
        __syncthreads();

        if (t < jbase) continue;
        const int jmax = min(t - jbase, 127);

        for (int j0 = 0; j0 <= jmax; j0 += 8) {
            float s[8];
#pragma unroll
            for (int i = 0; i < 8; ++i) {
                const ulonglong2* kr = (const ulonglong2*)(sK + (j0 + i) * HD_);
                u64 d0 = 0ull, d1 = 0ull, d2 = 0ull, d3 = 0ull;
#pragma unroll
                for (int c = 0; c < 12; c += 2) {
                    ulonglong2 k0 = kr[c];
                    ulonglong2 k1 = kr[c + 1];
                    d0 = fma2(q2[2 * c + 0], k0.x, d0);
                    d1 = fma2(q2[2 * c + 1], k0.y, d1);
                    d2 = fma2(q2[2 * c + 2], k1.x, d2);
                    d3 = fma2(q2[2 * c + 3], k1.y, d3);
                }
                const float2 sf = unpack2(add2(add2(d0, d1), add2(d2, d3)));
                const float dsum = sf.x + sf.y;
                s[i] = (j0 + i <= jmax) ? dsum * scale : NEG_INF;
            }
            float cm = s[0];
#pragma unroll
            for (int i = 1; i < 8; ++i) cm = fmaxf(cm, s[i]);
            const float mnew = fmaxf(mrow, cm);
            const float corr = __expf(mrow - mnew);   // exp(-inf)=0 on first chunk
            float p[8];
            float psum = 0.f;
#pragma unroll
            for (int i = 0; i < 8; ++i) { p[i] = __expf(s[i] - mnew); psum += p[i]; }
            l = l * corr + psum;
            const u64 corrp = pack2(corr, corr);
#pragma unroll
            for (int d = 0; d < 24; ++d) acc2[d] = mul2(acc2[d], corrp);
#pragma unroll
            for (int i = 0; i < 8; ++i) {
                const ulonglong2* vr = (const ulonglong2*)(sV + (j0 + i) * HD_);
                const u64 pp = pack2(p[i], p[i]);
#pragma unroll
                for (int c = 0; c < 12; ++c) {
                    ulonglong2 vv = vr[c];
                    acc2[2 * c + 0] = fma2(pp, vv.x, acc2[2 * c + 0]);
                    acc2[2 * c + 1] = fma2(pp, vv.y, acc2[2 * c + 1]);
                }
            }
            mrow = mnew;
        }
    }

    const float inv = 1.f / l;
    const u64 invp = pack2(inv, inv);
    const int b = bh >> 3, h = bh & 7;
    float* dst = g_att + (size_t)(b * T_ + t) * C_ + h * HD_;
#pragma unroll
    for (int c = 0; c < 12; ++c) {
        const float2 lo = unpack2(mul2(acc2[2 * c + 0], invp));
        const float2 hi = unpack2(mul2(acc2[2 * c + 1], invp));
        float4 v;
        v.x = lo.x; v.y = lo.y; v.z = hi.x; v.w = hi.y;
        ((float4*)dst)[c] = v;
    }
}

// ---------------------------------------------------------------------------
extern "C" void kernel_launch(void* const* d_in, const int* in_sizes, int n_in,
                              void* d_out, int out_size)
{
    const float* x      = (const float*)d_in[0];
    const float* attn_w = (const float*)d_in[1];
    const float* attn_b = (const float*)d_in[2];
    const float* proj_w = (const float*)d_in[3];
    const float* proj_b = (const float*)d_in[4];
    float* out = (float*)d_out;

    gemm_qkv_kernel<<<dim3(N1_ / 128, M_ / 128), 256>>>(x, attn_w, attn_b);
    attn_kernel<<<B_ * NH_, 256>>>();
    gemm_proj_kernel<<<dim3(C_ / 128, M_ / 128), 256>>>(proj_w, proj_b, out);
}

// round 5
// speedup vs baseline: 2.3448x; 1.0297x over previous
#include <cuda_runtime.h>
#include <stdint.h>

// Problem constants
#define B_   256
#define T_   256
#define C_   384
#define NH_  8
#define HD_  48
#define M_   (B_ * T_)        // 65536 rows
#define N1_  (3 * C_)         // 1152 qkv outputs
#define QKV_STRIDE 25165824   // B*T*C elements per q/k/v region

// Scratch (allocation-guard-safe: static __device__ globals)
__device__ float g_qkv[3ull * QKV_STRIDE];   // [3][B][NH][T][HD]
__device__ float g_att[(size_t)QKV_STRIDE];  // [B][T][C]

// ---------------------------------------------------------------------------
// tf32 / packed-f32x2 / cp.async helpers
// ---------------------------------------------------------------------------
__device__ __forceinline__ uint32_t f2tf(float f) {
    uint32_t u;
    asm("cvt.rna.tf32.f32 %0, %1;" : "=r"(u) : "f"(f));
    return u;
}

__device__ __forceinline__ void mma_tf32(
    float& c0, float& c1, float& c2, float& c3,
    uint32_t a0, uint32_t a1, uint32_t a2, uint32_t a3,
    uint32_t b0, uint32_t b1)
{
    asm volatile(
        "mma.sync.aligned.m16n8k8.row.col.f32.tf32.tf32.f32 "
        "{%0,%1,%2,%3}, {%4,%5,%6,%7}, {%8,%9}, {%0,%1,%2,%3};"
        : "+f"(c0), "+f"(c1), "+f"(c2), "+f"(c3)
        : "r"(a0), "r"(a1), "r"(a2), "r"(a3), "r"(b0), "r"(b1));
}

__device__ __forceinline__ void cpa16(uint32_t saddr, const void* g) {
    asm volatile("cp.async.ca.shared.global [%0], [%1], 16;"
                 :: "r"(saddr), "l"(g));
}
#define CP_COMMIT() asm volatile("cp.async.commit_group;")
#define CP_WAIT0()  asm volatile("cp.async.wait_group 0;")

typedef unsigned long long u64;

__device__ __forceinline__ u64 fma2(u64 a, u64 b, u64 c) {
    u64 d;
    asm("fma.rn.f32x2 %0, %1, %2, %3;" : "=l"(d) : "l"(a), "l"(b), "l"(c));
    return d;
}
__device__ __forceinline__ u64 mul2(u64 a, u64 b) {
    u64 d;
    asm("mul.rn.f32x2 %0, %1, %2;" : "=l"(d) : "l"(a), "l"(b));
    return d;
}
__device__ __forceinline__ u64 add2(u64 a, u64 b) {
    u64 d;
    asm("add.rn.f32x2 %0, %1, %2;" : "=l"(d) : "l"(a), "l"(b));
    return d;
}
__device__ __forceinline__ u64 pack2(float x, float y) {
    u64 d;
    asm("mov.b64 %0, {%1, %2};" : "=l"(d) : "f"(x), "f"(y));
    return d;
}
__device__ __forceinline__ float2 unpack2(u64 v) {
    float2 r;
    asm("mov.b64 {%0, %1}, %2;" : "=f"(r.x), "=f"(r.y) : "l"(v));
    return r;
}

// ---------------------------------------------------------------------------
// tf32 tensor-core GEMM core, cp.async double-buffered.
// 128x128 tile, BK=16, 256 thr = 8 warps (2m x 4n), warp 64x32 = 4x4 m16n8k8.
// Smem: raw fp32, m-major, row stride ASTR=20 words (80 B; 16B-aligned rows,
// and fragment reads (20*gid+ctg) mod 32 hit 32 distinct banks).
// f2tf conversion happens register-side after LDS (same k-order as before ->
// bit-identical accumulation vs R4).
// ---------------------------------------------------------------------------
#define ASTR    20
#define BUF_ELT (128 * ASTR)   // 2560 floats per buffer

struct GemmFrag {
    float acc[4][4][4];   // [m-atom][n-atom][reg]
    int gid, ctg, wmB, wnB;
};

__device__ __forceinline__ void gemm_core(
    const float* __restrict__ A, const float* __restrict__ W,
    int mBase, int nBase, float* As, float* Bs, GemmFrag& f)
{
    const int tid  = threadIdx.x;
    const int lane = tid & 31;
    const int warp = tid >> 5;
    f.gid = lane >> 2;
    f.ctg = lane & 3;
    f.wmB = (warp >> 2) * 64;
    f.wnB = (warp & 3) * 32;

#pragma unroll
    for (int i = 0; i < 4; ++i)
#pragma unroll
        for (int j = 0; j < 4; ++j)
#pragma unroll
            for (int r = 0; r < 4; ++r) f.acc[i][j][r] = 0.f;

    // cp.async mapping: thread handles rows lrow and lrow+64, k-chunk lkc.
    const int lrow = tid >> 2;          // 0..63
    const int lkc  = (tid & 3) * 4;     // 0,4,8,12
    const uint32_t sA = (uint32_t)__cvta_generic_to_shared(As)
                      + (uint32_t)((lrow * ASTR + lkc) * 4);
    const uint32_t sB = (uint32_t)__cvta_generic_to_shared(Bs)
                      + (uint32_t)((lrow * ASTR + lkc) * 4);
    const float* gA0 = A + (size_t)(mBase + lrow) * 384 + lkc;
    const float* gA1 = gA0 + (size_t)64 * 384;
    const float* gW0 = W + (size_t)(nBase + lrow) * 384 + lkc;
    const float* gW1 = gW0 + (size_t)64 * 384;

    // prologue: tile 0
    cpa16(sA,                 gA0);
    cpa16(sA + 64 * ASTR * 4, gA1);
    cpa16(sB,                 gW0);
    cpa16(sB + 64 * ASTR * 4, gW1);
    CP_COMMIT();

    const int a_m0 = f.wmB + f.gid;     // row base for a0/a2
    const int b_n0 = f.wnB + f.gid;

    for (int t = 0; t < 24; ++t) {
        CP_WAIT0();
        __syncthreads();   // tile t visible to all; prior reads of other buf done

        if (t < 23) {      // issue tile t+1 into the other buffer
            const uint32_t off = (t & 1) ? 0u : (uint32_t)(BUF_ELT * 4);
            const int kt = (t + 1) * 16;
            cpa16(sA + off,                 gA0 + kt);
            cpa16(sA + off + 64 * ASTR * 4, gA1 + kt);
            cpa16(sB + off,                 gW0 + kt);
            cpa16(sB + off + 64 * ASTR * 4, gW1 + kt);
            CP_COMMIT();
        }

        const float* Ab = As + (t & 1) * BUF_ELT;
        const float* Bb = Bs + (t & 1) * BUF_ELT;

#pragma unroll
        for (int kb = 0; kb < 16; kb += 8) {
            uint32_t a[4][4], b[4][2];
#pragma unroll
            for (int im = 0; im < 4; ++im) {
                const int m0 = a_m0 + im * 16;
                a[im][0] = f2tf(Ab[(m0)     * ASTR + kb + f.ctg]);
                a[im][1] = f2tf(Ab[(m0 + 8) * ASTR + kb + f.ctg]);
                a[im][2] = f2tf(Ab[(m0)     * ASTR + kb + f.ctg + 4]);
                a[im][3] = f2tf(Ab[(m0 + 8) * ASTR + kb + f.ctg + 4]);
            }
#pragma unroll
            for (int jn = 0; jn < 4; ++jn) {
                const int n0 = b_n0 + jn * 8;
                b[jn][0] = f2tf(Bb[n0 * ASTR + kb + f.ctg]);
                b[jn][1] = f2tf(Bb[n0 * ASTR + kb + f.ctg + 4]);
            }
#pragma unroll
            for (int im = 0; im < 4; ++im)
#pragma unroll
                for (int jn = 0; jn < 4; ++jn)
                    mma_tf32(f.acc[im][jn][0], f.acc[im][jn][1],
                             f.acc[im][jn][2], f.acc[im][jn][3],
                             a[im][0], a[im][1], a[im][2], a[im][3],
                             b[jn][0], b[jn][1]);
        }
        __syncthreads();   // all reads of this buffer done before refill
    }
}

// ---------------------------------------------------------------------------
// GEMM 1: qkv = x @ attn_w^T + attn_b, scattered head-major into g_qkv.
// ---------------------------------------------------------------------------
__global__ __launch_bounds__(256) void gemm_qkv_kernel(
    const float* __restrict__ A,
    const float* __restrict__ W,
    const float* __restrict__ bias)
{
    __shared__ float As[2 * BUF_ELT];
    __shared__ float Bs[2 * BUF_ELT];
    const int mBase = blockIdx.y * 128;
    const int nBase = blockIdx.x * 128;

    GemmFrag f;
    gemm_core(A, W, mBase, nBase, As, Bs, f);

#pragma unroll
    for (int im = 0; im < 4; ++im) {
#pragma unroll
        for (int jn = 0; jn < 4; ++jn) {
            const int col = nBase + f.wnB + jn * 8 + 2 * f.ctg;
            const float2 bi = *(const float2*)(bias + col);
            const int which = col / C_;
            const int c = col - which * C_;
            const int h = c / HD_;
            const int d = c - h * HD_;   // even; pair never straddles a head
#pragma unroll
            for (int half = 0; half < 2; ++half) {
                const int row = mBase + f.wmB + im * 16 + f.gid + half * 8;
                const int b = row >> 8;
                const int t = row & 255;
                float2 v;
                v.x = f.acc[im][jn][half * 2 + 0] + bi.x;
                v.y = f.acc[im][jn][half * 2 + 1] + bi.y;
                const size_t dst = (size_t)which * QKV_STRIDE
                                 + ((size_t)((b * NH_ + h) * T_ + t)) * HD_ + d;
                *(float2*)(g_qkv + dst) = v;
            }
        }
    }
}

// ---------------------------------------------------------------------------
// GEMM 2: out = g_att @ proj_w^T + proj_b.
// ---------------------------------------------------------------------------
__global__ __launch_bounds__(256) void gemm_proj_kernel(
    const float* __restrict__ W,
    const float* __restrict__ bias,
    float* __restrict__ out)
{
    __shared__ float As[2 * BUF_ELT];
    __shared__ float Bs[2 * BUF_ELT];
    const int mBase = blockIdx.y * 128;
    const int nBase = blockIdx.x * 128;

    GemmFrag f;
    gemm_core(g_att, W, mBase, nBase, As, Bs, f);

#pragma unroll
    for (int im = 0; im < 4; ++im) {
#pragma unroll
        for (int jn = 0; jn < 4; ++jn) {
            const int col = nBase + f.wnB + jn * 8 + 2 * f.ctg;
            const float2 bi = *(const float2*)(bias + col);
#pragma unroll
            for (int half = 0; half < 2; ++half) {
                const int row = mBase + f.wmB + im * 16 + f.gid + half * 8;
                float2 v;
                v.x = f.acc[im][jn][half * 2 + 0] + bi.x;
                v.y = f.acc[im][jn][half * 2 + 1] + bi.y;
                *(float2*)(out + (size_t)row * C_ + col) = v;
            }
        }
    }
}

// ---------------------------------------------------------------------------
// Attention: exact-fp32 flash attention using packed fma.rn.f32x2.
// (unchanged from R4 — isolates the GEMM pipeline change)
// ---------------------------------------------------------------------------
__global__ __launch_bounds__(256) void attn_kernel()
{
    __shared__ float sK[128 * HD_];
    __shared__ float sV[128 * HD_];

    const int bh = blockIdx.x;
    const size_t base = (size_t)bh * (T_ * HD_);
    const float* Qg = g_qkv + base;
    const float* Kg = g_qkv + (size_t)QKV_STRIDE + base;
    const float* Vg = g_qkv + 2ull * QKV_STRIDE + base;

    const int t = threadIdx.x;

    u64 q2[24];
    {
        const u64* qp = (const u64*)(Qg + (size_t)t * HD_);
#pragma unroll
        for (int i = 0; i < 24; ++i) q2[i] = qp[i];
    }

    const float scale   = 0.14433756729740645f;   // 1/sqrt(48)
    const float NEG_INF = __int_as_float(0xff800000);
    float mrow = NEG_INF;
    float l = 0.f;
    u64 acc2[24];
#pragma unroll
    for (int d = 0; d < 24; ++d) acc2[d] = 0ull;

    for (int tile = 0; tile < 2; ++tile) {
        const int jbase = tile * 128;
        __syncthreads();
#pragma unroll
        for (int i = 0; i < 6; ++i) {
            const int idx = t + i * 256;
            ((float4*)sK)[idx] = ((const float4*)(Kg + (size_t)jbase * HD_))[idx];
            ((float4*)sV)[idx] = ((const float4*)(Vg + (size_t)jbase * HD_))[idx];
        }
        __syncthreads();

        if (t < jbase) continue;
        const int jmax = min(t - jbase, 127);

        for (int j0 = 0; j0 <= jmax; j0 += 8) {
            float s[8];
#pragma unroll
            for (int i = 0; i < 8; ++i) {
                const ulonglong2* kr = (const ulonglong2*)(sK + (j0 + i) * HD_);
                u64 d0 = 0ull, d1 = 0ull, d2 = 0ull, d3 = 0ull;
#pragma unroll
                for (int c = 0; c < 12; c += 2) {
                    ulonglong2 k0 = kr[c];
                    ulonglong2 k1 = kr[c + 1];
                    d0 = fma2(q2[2 * c + 0], k0.x, d0);
                    d1 = fma2(q2[2 * c + 1], k0.y, d1);
                    d2 = fma2(q2[2 * c + 2], k1.x, d2);
                    d3 = fma2(q2[2 * c + 3], k1.y, d3);
                }
                const float2 sf = unpack2(add2(add2(d0, d1), add2(d2, d3)));
                const float dsum = sf.x + sf.y;
                s[i] = (j0 + i <= jmax) ? dsum * scale : NEG_INF;
            }
            float cm = s[0];
#pragma unroll
            for (int i = 1; i < 8; ++i) cm = fmaxf(cm, s[i]);
            const float mnew = fmaxf(mrow, cm);
            const float corr = __expf(mrow - mnew);   // exp(-inf)=0 on first chunk
            float p[8];
            float psum = 0.f;
#pragma unroll
            for (int i = 0; i < 8; ++i) { p[i] = __expf(s[i] - mnew); psum += p[i]; }
            l = l * corr + psum;
            const u64 corrp = pack2(corr, corr);
#pragma unroll
            for (int d = 0; d < 24; ++d) acc2[d] = mul2(acc2[d], corrp);
#pragma unroll
            for (int i = 0; i < 8; ++i) {
                const ulonglong2* vr = (const ulonglong2*)(sV + (j0 + i) * HD_);
                const u64 pp = pack2(p[i], p[i]);
#pragma unroll
                for (int c = 0; c < 12; ++c) {
                    ulonglong2 vv = vr[c];
                    acc2[2 * c + 0] = fma2(pp, vv.x, acc2[2 * c + 0]);
                    acc2[2 * c + 1] = fma2(pp, vv.y, acc2[2 * c + 1]);
                }
            }
            mrow = mnew;
        }
    }

    const float inv = 1.f / l;
    const u64 invp = pack2(inv, inv);
    const int b = bh >> 3, h = bh & 7;
    float* dst = g_att + (size_t)(b * T_ + t) * C_ + h * HD_;
#pragma unroll
    for (int c = 0; c < 12; ++c) {
        const float2 lo = unpack2(mul2(acc2[2 * c + 0], invp));
        const float2 hi = unpack2(mul2(acc2[2 * c + 1], invp));
        float4 v;
        v.x = lo.x; v.y = lo.y; v.z = hi.x; v.w = hi.y;
        ((float4*)dst)[c] = v;
    }
}

// ---------------------------------------------------------------------------
extern "C" void kernel_launch(void* const* d_in, const int* in_sizes, int n_in,
                              void* d_out, int out_size)
{
    const float* x      = (const float*)d_in[0];
    const float* attn_w = (const float*)d_in[1];
    const float* attn_b = (const float*)d_in[2];
    const float* proj_w = (const float*)d_in[3];
    const float* proj_b = (const float*)d_in[4];
    float* out = (float*)d_out;

    gemm_qkv_kernel<<<dim3(N1_ / 128, M_ / 128), 256>>>(x, attn_w, attn_b);
    attn_kernel<<<B_ * NH_, 256>>>();
    gemm_proj_kernel<<<dim3(C_ / 128, M_ / 128), 256>>>(proj_w, proj_b, out);
}

// round 6
// speedup vs baseline: 3.1152x; 1.3285x over previous
#include <cuda_runtime.h>
#include <stdint.h>

// Problem constants
#define B_   256
#define T_   256
#define C_   384
#define NH_  8
#define HD_  48
#define M_   (B_ * T_)        // 65536 rows
#define N1_  (3 * C_)         // 1152 qkv outputs
#define QKV_STRIDE 25165824   // B*T*C elements per q/k/v region

// Scratch (allocation-guard-safe: static __device__ globals)
__device__ float g_qkv[3ull * QKV_STRIDE];   // [3][B][NH][T][HD]
__device__ float g_att[(size_t)QKV_STRIDE];  // [B][T][C]

// ---------------------------------------------------------------------------
// tf32 / cp.async helpers
// ---------------------------------------------------------------------------
__device__ __forceinline__ uint32_t f2tf(float f) {
    uint32_t u;
    asm("cvt.rna.tf32.f32 %0, %1;" : "=r"(u) : "f"(f));
    return u;
}

__device__ __forceinline__ void mma_tf32(
    float& c0, float& c1, float& c2, float& c3,
    uint32_t a0, uint32_t a1, uint32_t a2, uint32_t a3,
    uint32_t b0, uint32_t b1)
{
    asm volatile(
        "mma.sync.aligned.m16n8k8.row.col.f32.tf32.tf32.f32 "
        "{%0,%1,%2,%3}, {%4,%5,%6,%7}, {%8,%9}, {%0,%1,%2,%3};"
        : "+f"(c0), "+f"(c1), "+f"(c2), "+f"(c3)
        : "r"(a0), "r"(a1), "r"(a2), "r"(a3), "r"(b0), "r"(b1));
}

__device__ __forceinline__ void cpa16(uint32_t saddr, const void* g) {
    asm volatile("cp.async.ca.shared.global [%0], [%1], 16;"
                 :: "r"(saddr), "l"(g));
}
#define CP_COMMIT() asm volatile("cp.async.commit_group;")
#define CP_WAIT0()  asm volatile("cp.async.wait_group 0;")

// ---------------------------------------------------------------------------
// tf32 tensor-core GEMM core, cp.async double-buffered (unchanged from R5).
// ---------------------------------------------------------------------------
#define ASTR    20
#define BUF_ELT (128 * ASTR)   // 2560 floats per buffer

struct GemmFrag {
    float acc[4][4][4];   // [m-atom][n-atom][reg]
    int gid, ctg, wmB, wnB;
};

__device__ __forceinline__ void gemm_core(
    const float* __restrict__ A, const float* __restrict__ W,
    int mBase, int nBase, float* As, float* Bs, GemmFrag& f)
{
    const int tid  = threadIdx.x;
    const int lane = tid & 31;
    const int warp = tid >> 5;
    f.gid = lane >> 2;
    f.ctg = lane & 3;
    f.wmB = (warp >> 2) * 64;
    f.wnB = (warp & 3) * 32;

#pragma unroll
    for (int i = 0; i < 4; ++i)
#pragma unroll
        for (int j = 0; j < 4; ++j)
#pragma unroll
            for (int r = 0; r < 4; ++r) f.acc[i][j][r] = 0.f;

    const int lrow = tid >> 2;          // 0..63
    const int lkc  = (tid & 3) * 4;     // 0,4,8,12
    const uint32_t sA = (uint32_t)__cvta_generic_to_shared(As)
                      + (uint32_t)((lrow * ASTR + lkc) * 4);
    const uint32_t sB = (uint32_t)__cvta_generic_to_shared(Bs)
                      + (uint32_t)((lrow * ASTR + lkc) * 4);
    const float* gA0 = A + (size_t)(mBase + lrow) * 384 + lkc;
    const float* gA1 = gA0 + (size_t)64 * 384;
    const float* gW0 = W + (size_t)(nBase + lrow) * 384 + lkc;
    const float* gW1 = gW0 + (size_t)64 * 384;

    cpa16(sA,                 gA0);
    cpa16(sA + 64 * ASTR * 4, gA1);
    cpa16(sB,                 gW0);
    cpa16(sB + 64 * ASTR * 4, gW1);
    CP_COMMIT();

    const int a_m0 = f.wmB + f.gid;
    const int b_n0 = f.wnB + f.gid;

    for (int t = 0; t < 24; ++t) {
        CP_WAIT0();
        __syncthreads();

        if (t < 23) {
            const uint32_t off = (t & 1) ? 0u : (uint32_t)(BUF_ELT * 4);
            const int kt = (t + 1) * 16;
            cpa16(sA + off,                 gA0 + kt);
            cpa16(sA + off + 64 * ASTR * 4, gA1 + kt);
            cpa16(sB + off,                 gW0 + kt);
            cpa16(sB + off + 64 * ASTR * 4, gW1 + kt);
            CP_COMMIT();
        }

        const float* Ab = As + (t & 1) * BUF_ELT;
        const float* Bb = Bs + (t & 1) * BUF_ELT;

#pragma unroll
        for (int kb = 0; kb < 16; kb += 8) {
            uint32_t a[4][4], b[4][2];
#pragma unroll
            for (int im = 0; im < 4; ++im) {
                const int m0 = a_m0 + im * 16;
                a[im][0] = f2tf(Ab[(m0)     * ASTR + kb + f.ctg]);
                a[im][1] = f2tf(Ab[(m0 + 8) * ASTR + kb + f.ctg]);
                a[im][2] = f2tf(Ab[(m0)     * ASTR + kb + f.ctg + 4]);
                a[im][3] = f2tf(Ab[(m0 + 8) * ASTR + kb + f.ctg + 4]);
            }
#pragma unroll
            for (int jn = 0; jn < 4; ++jn) {
                const int n0 = b_n0 + jn * 8;
                b[jn][0] = f2tf(Bb[n0 * ASTR + kb + f.ctg]);
                b[jn][1] = f2tf(Bb[n0 * ASTR + kb + f.ctg + 4]);
            }
#pragma unroll
            for (int im = 0; im < 4; ++im)
#pragma unroll
                for (int jn = 0; jn < 4; ++jn)
                    mma_tf32(f.acc[im][jn][0], f.acc[im][jn][1],
                             f.acc[im][jn][2], f.acc[im][jn][3],
                             a[im][0], a[im][1], a[im][2], a[im][3],
                             b[jn][0], b[jn][1]);
        }
        __syncthreads();
    }
}

// ---------------------------------------------------------------------------
// GEMM 1: qkv = x @ attn_w^T + attn_b, scattered head-major into g_qkv.
// ---------------------------------------------------------------------------
__global__ __launch_bounds__(256) void gemm_qkv_kernel(
    const float* __restrict__ A,
    const float* __restrict__ W,
    const float* __restrict__ bias)
{
    __shared__ float As[2 * BUF_ELT];
    __shared__ float Bs[2 * BUF_ELT];
    const int mBase = blockIdx.y * 128;
    const int nBase = blockIdx.x * 128;

    GemmFrag f;
    gemm_core(A, W, mBase, nBase, As, Bs, f);

#pragma unroll
    for (int im = 0; im < 4; ++im) {
#pragma unroll
        for (int jn = 0; jn < 4; ++jn) {
            const int col = nBase + f.wnB + jn * 8 + 2 * f.ctg;
            const float2 bi = *(const float2*)(bias + col);
            const int which = col / C_;
            const int c = col - which * C_;
            const int h = c / HD_;
            const int d = c - h * HD_;
#pragma unroll
            for (int half = 0; half < 2; ++half) {
                const int row = mBase + f.wmB + im * 16 + f.gid + half * 8;
                const int b = row >> 8;
                const int t = row & 255;
                float2 v;
                v.x = f.acc[im][jn][half * 2 + 0] + bi.x;
                v.y = f.acc[im][jn][half * 2 + 1] + bi.y;
                const size_t dst = (size_t)which * QKV_STRIDE
                                 + ((size_t)((b * NH_ + h) * T_ + t)) * HD_ + d;
                *(float2*)(g_qkv + dst) = v;
            }
        }
    }
}

// ---------------------------------------------------------------------------
// GEMM 2: out = g_att @ proj_w^T + proj_b.
// ---------------------------------------------------------------------------
__global__ __launch_bounds__(256) void gemm_proj_kernel(
    const float* __restrict__ W,
    const float* __restrict__ bias,
    float* __restrict__ out)
{
    __shared__ float As[2 * BUF_ELT];
    __shared__ float Bs[2 * BUF_ELT];
    const int mBase = blockIdx.y * 128;
    const int nBase = blockIdx.x * 128;

    GemmFrag f;
    gemm_core(g_att, W, mBase, nBase, As, Bs, f);

#pragma unroll
    for (int im = 0; im < 4; ++im) {
#pragma unroll
        for (int jn = 0; jn < 4; ++jn) {
            const int col = nBase + f.wnB + jn * 8 + 2 * f.ctg;
            const float2 bi = *(const float2*)(bias + col);
#pragma unroll
            for (int half = 0; half < 2; ++half) {
                const int row = mBase + f.wmB + im * 16 + f.gid + half * 8;
                float2 v;
                v.x = f.acc[im][jn][half * 2 + 0] + bi.x;
                v.y = f.acc[im][jn][half * 2 + 1] + bi.y;
                *(float2*)(out + (size_t)row * C_ + col) = v;
            }
        }
    }
}

// ---------------------------------------------------------------------------
// Flash attention, tf32 tensor cores.
// CTA = 128 q-rows of one (b,h).  grid (2048, 2).  256 thr = 8 warps;
// each warp owns 16 full rows (m16 atom), so softmax is warp-local.
// j-tiles of 64 keys.  K smem [64][52] tf32, V^T smem [48][68] tf32.
// P (S-frag) -> A-frag via intra-quad shuffles (no smem roundtrip).
// ---------------------------------------------------------------------------
#define KSTR 52
#define VSTR 68

__global__ __launch_bounds__(256) void attn_kernel()
{
    __shared__ uint32_t sK[64 * KSTR];
    __shared__ uint32_t sVT[48 * VSTR];

    const int bh = blockIdx.x;
    const int qt = blockIdx.y;
    const int qb = qt * 128;
    const size_t base = (size_t)bh * (T_ * HD_);
    const float* Qg = g_qkv + base;
    const float* Kg = g_qkv + (size_t)QKV_STRIDE + base;
    const float* Vg = g_qkv + 2ull * QKV_STRIDE + base;

    const int tid  = threadIdx.x;
    const int lane = tid & 31;
    const int wid  = tid >> 5;
    const int gid  = lane >> 2;
    const int ctg  = lane & 3;

    const int r0  = wid * 16 + gid;      // local row within q-tile
    const int r1  = r0 + 8;
    const int gr0 = qb + r0;             // global rows
    const int gr1 = qb + r1;

    const float scale   = 0.14433756729740645f;   // 1/sqrt(48)
    const float NEG_INF = __int_as_float(0xff800000);

    // Q -> register A-fragments (pre-scaled)
    uint32_t aq[6][4];
#pragma unroll
    for (int kb = 0; kb < 6; ++kb) {
        aq[kb][0] = f2tf(Qg[(size_t)gr0 * HD_ + kb * 8 + ctg]     * scale);
        aq[kb][1] = f2tf(Qg[(size_t)gr1 * HD_ + kb * 8 + ctg]     * scale);
        aq[kb][2] = f2tf(Qg[(size_t)gr0 * HD_ + kb * 8 + ctg + 4] * scale);
        aq[kb][3] = f2tf(Qg[(size_t)gr1 * HD_ + kb * 8 + ctg + 4] * scale);
    }

    float m0 = NEG_INF, m1 = NEG_INF, l0 = 0.f, l1 = 0.f;
    float o[6][4];
#pragma unroll
    for (int n = 0; n < 6; ++n)
#pragma unroll
        for (int r = 0; r < 4; ++r) o[n][r] = 0.f;

    const int npass = 2 * (qt + 1);
    for (int j = 0; j < npass; ++j) {
        const int jb = j * 64;
        __syncthreads();   // previous tile fully consumed

        // stage K[jb..jb+63][48] and V^T (both tf32)
#pragma unroll
        for (int i = 0; i < 3; ++i) {
            const int idx = tid + i * 256;       // 0..767
            const int r   = idx / 12;
            const int c4  = (idx % 12) * 4;
            const float4 kv = *(const float4*)(Kg + (size_t)(jb + r) * HD_ + c4);
            uint4 kt;
            kt.x = f2tf(kv.x); kt.y = f2tf(kv.y);
            kt.z = f2tf(kv.z); kt.w = f2tf(kv.w);
            *(uint4*)(sK + r * KSTR + c4) = kt;
            const float4 vv = *(const float4*)(Vg + (size_t)(jb + r) * HD_ + c4);
            sVT[(c4 + 0) * VSTR + r] = f2tf(vv.x);
            sVT[(c4 + 1) * VSTR + r] = f2tf(vv.y);
            sVT[(c4 + 2) * VSTR + r] = f2tf(vv.z);
            sVT[(c4 + 3) * VSTR + r] = f2tf(vv.w);
        }
        __syncthreads();

        // warp-uniform causal skip: warp rows all < jb  (both mult of 16)
        if (jb > qb + wid * 16 + 15) continue;

        // --- S = Q K^T : 8 n-atoms of 8 keys ---
        float s[8][4];
#pragma unroll
        for (int nb = 0; nb < 8; ++nb) {
            s[nb][0] = 0.f; s[nb][1] = 0.f; s[nb][2] = 0.f; s[nb][3] = 0.f;
#pragma unroll
            for (int kb = 0; kb < 6; ++kb) {
                const uint32_t b0 = sK[(nb * 8 + gid) * KSTR + kb * 8 + ctg];
                const uint32_t b1 = sK[(nb * 8 + gid) * KSTR + kb * 8 + ctg + 4];
                mma_tf32(s[nb][0], s[nb][1], s[nb][2], s[nb][3],
                         aq[kb][0], aq[kb][1], aq[kb][2], aq[kb][3], b0, b1);
            }
        }

        // --- mask + online softmax (warp-local; rows split per lane quad) ---
        float tmax0 = NEG_INF, tmax1 = NEG_INF;
#pragma unroll
        for (int nb = 0; nb < 8; ++nb) {
            const int k0 = jb + nb * 8 + 2 * ctg;
            const int k1 = k0 + 1;
            if (k0 > gr0) s[nb][0] = NEG_INF;
            if (k1 > gr0) s[nb][1] = NEG_INF;
            if (k0 > gr1) s[nb][2] = NEG_INF;
            if (k1 > gr1) s[nb][3] = NEG_INF;
            tmax0 = fmaxf(tmax0, fmaxf(s[nb][0], s[nb][1]));
            tmax1 = fmaxf(tmax1, fmaxf(s[nb][2], s[nb][3]));
        }
        tmax0 = fmaxf(tmax0, __shfl_xor_sync(0xffffffffu, tmax0, 1));
        tmax0 = fmaxf(tmax0, __shfl_xor_sync(0xffffffffu, tmax0, 2));
        tmax1 = fmaxf(tmax1, __shfl_xor_sync(0xffffffffu, tmax1, 1));
        tmax1 = fmaxf(tmax1, __shfl_xor_sync(0xffffffffu, tmax1, 2));

        const float mn0 = fmaxf(m0, tmax0);
        const float mn1 = fmaxf(m1, tmax1);
        const float corr0 = __expf(m0 - mn0);   // m0=-inf only when tmax0=-inf impossible (jb<=rows)
        const float corr1 = __expf(m1 - mn1);
        m0 = mn0; m1 = mn1;

        float ps0 = 0.f, ps1 = 0.f;
#pragma unroll
        for (int nb = 0; nb < 8; ++nb) {
            s[nb][0] = __expf(s[nb][0] - mn0);
            s[nb][1] = __expf(s[nb][1] - mn0);
            s[nb][2] = __expf(s[nb][2] - mn1);
            s[nb][3] = __expf(s[nb][3] - mn1);
            ps0 += s[nb][0] + s[nb][1];
            ps1 += s[nb][2] + s[nb][3];
        }
        ps0 += __shfl_xor_sync(0xffffffffu, ps0, 1);
        ps0 += __shfl_xor_sync(0xffffffffu, ps0, 2);
        ps1 += __shfl_xor_sync(0xffffffffu, ps1, 1);
        ps1 += __shfl_xor_sync(0xffffffffu, ps1, 2);
        l0 = l0 * corr0 + ps0;
        l1 = l1 * corr1 + ps1;

#pragma unroll
        for (int n = 0; n < 6; ++n) {
            o[n][0] *= corr0; o[n][1] *= corr0;
            o[n][2] *= corr1; o[n][3] *= corr1;
        }

        // --- PV: for each k-atom, build P A-fragment via quad shuffles ---
        const int src0 = (lane & ~3) | (ctg >> 1);
        const int src1 = src0 + 2;
        const bool odd = ctg & 1;
#pragma unroll
        for (int kb = 0; kb < 8; ++kb) {
            const float v00 = __shfl_sync(0xffffffffu, s[kb][0], src0);
            const float v01 = __shfl_sync(0xffffffffu, s[kb][1], src0);
            const float v02 = __shfl_sync(0xffffffffu, s[kb][2], src0);
            const float v03 = __shfl_sync(0xffffffffu, s[kb][3], src0);
            const float v10 = __shfl_sync(0xffffffffu, s[kb][0], src1);
            const float v11 = __shfl_sync(0xffffffffu, s[kb][1], src1);
            const float v12 = __shfl_sync(0xffffffffu, s[kb][2], src1);
            const float v13 = __shfl_sync(0xffffffffu, s[kb][3], src1);
            uint32_t a0 = f2tf(odd ? v01 : v00);
            uint32_t a1 = f2tf(odd ? v03 : v02);
            uint32_t a2 = f2tf(odd ? v11 : v10);
            uint32_t a3 = f2tf(odd ? v13 : v12);
#pragma unroll
            for (int nb = 0; nb < 6; ++nb) {
                const uint32_t b0 = sVT[(nb * 8 + gid) * VSTR + kb * 8 + ctg];
                const uint32_t b1 = sVT[(nb * 8 + gid) * VSTR + kb * 8 + ctg + 4];
                mma_tf32(o[nb][0], o[nb][1], o[nb][2], o[nb][3],
                         a0, a1, a2, a3, b0, b1);
            }
        }
    }

    // epilogue: normalize, write g_att [b][t][C] at head column block
    const float inv0 = 1.f / l0;
    const float inv1 = 1.f / l1;
    const int b = bh >> 3, h = bh & 7;
    float* dst0 = g_att + (size_t)(b * T_ + gr0) * C_ + h * HD_;
    float* dst1 = g_att + (size_t)(b * T_ + gr1) * C_ + h * HD_;
#pragma unroll
    for (int nb = 0; nb < 6; ++nb) {
        const int col = nb * 8 + 2 * ctg;
        float2 v0, v1;
        v0.x = o[nb][0] * inv0; v0.y = o[nb][1] * inv0;
        v1.x = o[nb][2] * inv1; v1.y = o[nb][3] * inv1;
        *(float2*)(dst0 + col) = v0;
        *(float2*)(dst1 + col) = v1;
    }
}

// ---------------------------------------------------------------------------
extern "C" void kernel_launch(void* const* d_in, const int* in_sizes, int n_in,
                              void* d_out, int out_size)
{
    const float* x      = (const float*)d_in[0];
    const float* attn_w = (const float*)d_in[1];
    const float* attn_b = (const float*)d_in[2];
    const float* proj_w = (const float*)d_in[3];
    const float* proj_b = (const float*)d_in[4];
    float* out = (float*)d_out;

    gemm_qkv_kernel<<<dim3(N1_ / 128, M_ / 128), 256>>>(x, attn_w, attn_b);
    attn_kernel<<<dim3(B_ * NH_, 2), 256>>>();
    gemm_proj_kernel<<<dim3(C_ / 128, M_ / 128), 256>>>(proj_w, proj_b, out);
}